// round 16
// baseline (speedup 1.0000x reference)
#include <cuda_runtime.h>
#include <cuda_fp16.h>
#include <cstdint>

// ---------------------------------------------------------------------------
#define BATCH 4
#define SEQ 2048
#define ROWS (BATCH * SEQ)       // 8192
#define DMODEL 1024
#define NHEADS 16
#define DHEAD 64
#define DFF 4096

// ---------------------------------------------------------------------------
// Scratch (static device globals; no allocation allowed)
// ---------------------------------------------------------------------------
__device__ __half g_xh[ROWS * DMODEL];
__device__ __half g_xl[ROWS * DMODEL];
__device__ __half g_wqTh[DMODEL * DMODEL];   // [N,K] hi
__device__ __half g_wqTl[DMODEL * DMODEL];
__device__ __half g_wkTh[DMODEL * DMODEL];
__device__ __half g_wkTl[DMODEL * DMODEL];
__device__ __half g_wvT[DMODEL * DMODEL];
__device__ __half g_woT[DMODEL * DMODEL];
__device__ __half g_w1T[DMODEL * DFF];       // [DFF, DMODEL]
__device__ __half g_w2T[DFF * DMODEL];       // [DMODEL, DFF]

__device__ __half g_qrh[ROWS * DMODEL];
__device__ __half g_qrl[ROWS * DMODEL];
__device__ __half g_krh[ROWS * DMODEL];
__device__ __half g_krl[ROWS * DMODEL];
__device__ __half g_vh[ROWS * DMODEL];
__device__ __half g_ctx[ROWS * DMODEL];
__device__ float  g_res1[ROWS * DMODEL];
__device__ float  g_hbuf[ROWS * DMODEL];
__device__ __half g_hh[ROWS * DMODEL];
__device__ __half g_ff1[ROWS * DFF];
__device__ float  g_res2[ROWS * DMODEL];

// ---------------------------------------------------------------------------
// cp.async + mma helpers
// ---------------------------------------------------------------------------
__device__ __forceinline__ void cp16(void* s, const void* g) {
    unsigned int sa = (unsigned int)__cvta_generic_to_shared(s);
    asm volatile("cp.async.cg.shared.global [%0], [%1], 16;\n" :: "r"(sa), "l"(g) : "memory");
}
__device__ __forceinline__ void cp_commit() {
    asm volatile("cp.async.commit_group;\n" ::: "memory");
}
template<int N> __device__ __forceinline__ void cp_wait() {
    asm volatile("cp.async.wait_group %0;\n" :: "n"(N) : "memory");
}

__device__ __forceinline__ void mma16816(float* c, const uint32_t* a,
                                         uint32_t b0, uint32_t b1) {
    asm volatile(
        "mma.sync.aligned.m16n8k16.row.col.f32.f16.f16.f32 "
        "{%0,%1,%2,%3}, {%4,%5,%6,%7}, {%8,%9}, {%0,%1,%2,%3};\n"
        : "+f"(c[0]), "+f"(c[1]), "+f"(c[2]), "+f"(c[3])
        : "r"(a[0]), "r"(a[1]), "r"(a[2]), "r"(a[3]), "r"(b0), "r"(b1));
}
__device__ __forceinline__ uint32_t h2u(__half a, __half b) {
    __half2 t = __halves2half2(a, b);
    return *(uint32_t*)&t;
}
__device__ __forceinline__ uint32_t f2u2(float a, float b) {
    __half2 t = __floats2half2_rn(a, b);
    return *(uint32_t*)&t;
}

// ---------------------------------------------------------------------------
// x conversion (hi/lo split), tiled transpose-convert for weights
// ---------------------------------------------------------------------------
#define X4 (ROWS * DMODEL / 4)

__global__ void __launch_bounds__(256) convx_kernel(const float* __restrict__ in,
                                                    __half* __restrict__ hi,
                                                    __half* __restrict__ lo) {
    int i = blockIdx.x * 256 + threadIdx.x;
    if (i < X4) {
        float4 v = ((const float4*)in)[i];
        __half hx = __float2half(v.x), hy = __float2half(v.y);
        __half hz = __float2half(v.z), hw = __float2half(v.w);
        ((__half2*)hi)[2 * i]     = __halves2half2(hx, hy);
        ((__half2*)hi)[2 * i + 1] = __halves2half2(hz, hw);
        ((__half2*)lo)[2 * i]     = __floats2half2_rn(v.x - __half2float(hx),
                                                      v.y - __half2float(hy));
        ((__half2*)lo)[2 * i + 1] = __floats2half2_rn(v.z - __half2float(hz),
                                                      v.w - __half2float(hw));
    }
}

// w [K,N] fp32 -> wT [N,K] fp16 (plain). grid (N/32, K/32), 256 threads.
__global__ void __launch_bounds__(256) tconv_plain(const float* __restrict__ w,
                                                   __half* __restrict__ wT,
                                                   int K, int N) {
    __shared__ float t[32][33];
    int n0 = blockIdx.x * 32, k0 = blockIdx.y * 32;
    int tx = threadIdx.x & 31, ty = threadIdx.x >> 5;
#pragma unroll
    for (int i = 0; i < 4; i++)
        t[ty + i * 8][tx] = w[(size_t)(k0 + ty + i * 8) * N + n0 + tx];
    __syncthreads();
#pragma unroll
    for (int i = 0; i < 4; i++)
        wT[(size_t)(n0 + ty + i * 8) * K + k0 + tx] = __float2half(t[tx][ty + i * 8]);
}

// w [K,N] fp32 -> wT hi/lo [N,K] fp16 split.
__global__ void __launch_bounds__(256) tconv_split(const float* __restrict__ w,
                                                   __half* __restrict__ hiT,
                                                   __half* __restrict__ loT,
                                                   int K, int N) {
    __shared__ float t[32][33];
    int n0 = blockIdx.x * 32, k0 = blockIdx.y * 32;
    int tx = threadIdx.x & 31, ty = threadIdx.x >> 5;
#pragma unroll
    for (int i = 0; i < 4; i++)
        t[ty + i * 8][tx] = w[(size_t)(k0 + ty + i * 8) * N + n0 + tx];
    __syncthreads();
#pragma unroll
    for (int i = 0; i < 4; i++) {
        float v = t[tx][ty + i * 8];
        __half h = __float2half(v);
        size_t o = (size_t)(n0 + ty + i * 8) * K + k0 + tx;
        hiT[o] = h;
        loT[o] = __float2half(v - __half2float(h));
    }
}

// ---------------------------------------------------------------------------
// Raw-mma plain fp16 GEMM: C[M,N] = A[M,K] @ BT[N,K]^T + bias (+epilogues).
// 128x128x32 tiles, 8 warps (4x2), warp tile 32x64 (2 m-tiles x 8 n8-tiles).
// Smem rows x pitch-40 halfs -> per-lane 4B fragment loads are a perfect bank
// permutation. 3-stage cp.async. Acc order == wmma -> bit-identical.
// Each stage operand = 128 rows x 32 halfs = 512 16B-chunks (2 per thread).
// ---------------------------------------------------------------------------
#define GR_STG_H 10240
#define GR_SMEM 67584

template<bool RELU, bool RESID, bool WF32, bool WF16>
__global__ void __launch_bounds__(256) gemm_r(
    const __half* __restrict__ A, const __half* __restrict__ BT,
    const float* __restrict__ bias, const float* __restrict__ resid,
    float* __restrict__ Cf, __half* __restrict__ Ch,
    int M, int N, int K)
{
    extern __shared__ __align__(16) unsigned char sm[];
    __half* SH = (__half*)sm;

    const int tid = threadIdx.x;
    const int warp = tid >> 5;
    const int lane = tid & 31;
    const int gid = lane >> 2;        // 0..7
    const int qc  = (lane & 3) * 2;   // 0,2,4,6
    const int wm = warp >> 1;         // 0..3
    const int wn = warp & 1;          // 0..1
    const int row0 = blockIdx.y * 128;
    const int col0 = blockIdx.x * 128;

    float acc[2][8][4];
#pragma unroll
    for (int i = 0; i < 2; i++)
#pragma unroll
        for (int t = 0; t < 8; t++)
            acc[i][t][0] = acc[i][t][1] = acc[i][t][2] = acc[i][t][3] = 0.f;

    auto load_stage = [&](int k0, int s) {
        __half* base = SH + s * GR_STG_H;
#pragma unroll
        for (int i = 0; i < 2; i++) {          // A: 512 chunks
            int c = tid + i * 256;
            int r = c >> 2, q = c & 3;
            cp16(base + r * 40 + q * 8, A + (size_t)(row0 + r) * K + k0 + q * 8);
        }
#pragma unroll
        for (int i = 0; i < 2; i++) {          // B: 512 chunks
            int c = tid + i * 256;
            int r = c >> 2, q = c & 3;
            cp16(base + 5120 + r * 40 + q * 8, BT + (size_t)(col0 + r) * K + k0 + q * 8);
        }
    };

    const int nk = K >> 5;
    load_stage(0, 0); cp_commit();
    load_stage(32, 1); cp_commit();
    for (int kt = 0; kt < nk; kt++) {
        if (kt + 1 < nk) cp_wait<1>(); else cp_wait<0>();
        __syncthreads();
        if (kt + 2 < nk) { load_stage((kt + 2) << 5, (kt + 2) % 3); cp_commit(); }
        const __half* As = SH + (kt % 3) * GR_STG_H;
        const __half* Bs = As + 5120;
#pragma unroll
        for (int kc = 0; kc < 2; kc++) {
            uint32_t a[2][4];
#pragma unroll
            for (int i = 0; i < 2; i++) {
                const __half* ab = As + (wm * 32 + i * 16) * 40 + kc * 16;
                a[i][0] = *(const uint32_t*)(ab + gid * 40 + qc);
                a[i][1] = *(const uint32_t*)(ab + (gid + 8) * 40 + qc);
                a[i][2] = *(const uint32_t*)(ab + gid * 40 + qc + 8);
                a[i][3] = *(const uint32_t*)(ab + (gid + 8) * 40 + qc + 8);
            }
#pragma unroll
            for (int t = 0; t < 8; t++) {
                const __half* bb = Bs + (wn * 64 + t * 8 + gid) * 40 + kc * 16 + qc;
                uint32_t b0 = *(const uint32_t*)(bb);
                uint32_t b1 = *(const uint32_t*)(bb + 8);
#pragma unroll
                for (int i = 0; i < 2; i++)
                    mma16816(acc[i][t], a[i], b0, b1);
            }
        }
    }
    __syncthreads();

    float* stg = (float*)sm;
#pragma unroll
    for (int i = 0; i < 2; i++)
#pragma unroll
        for (int t = 0; t < 8; t++) {
            int rb = wm * 32 + i * 16;
            int cb = wn * 64 + t * 8 + qc;
            stg[(rb + gid) * 132 + cb]     = acc[i][t][0];
            stg[(rb + gid) * 132 + cb + 1] = acc[i][t][1];
            stg[(rb + gid + 8) * 132 + cb]     = acc[i][t][2];
            stg[(rb + gid + 8) * 132 + cb + 1] = acc[i][t][3];
        }
    __syncthreads();

#pragma unroll
    for (int e = 0; e < 16; e++) {
        int idx = tid + e * 256;
        int r = idx >> 5, c4 = idx & 31;
        float4 v;
        v.x = stg[r * 132 + c4 * 4 + 0];
        v.y = stg[r * 132 + c4 * 4 + 1];
        v.z = stg[r * 132 + c4 * 4 + 2];
        v.w = stg[r * 132 + c4 * 4 + 3];
        float4 bb = *(const float4*)(bias + col0 + c4 * 4);
        v.x += bb.x; v.y += bb.y; v.z += bb.z; v.w += bb.w;
        if (RELU) { v.x = fmaxf(v.x, 0.f); v.y = fmaxf(v.y, 0.f); v.z = fmaxf(v.z, 0.f); v.w = fmaxf(v.w, 0.f); }
        size_t g = (size_t)(row0 + r) * N + col0 + c4 * 4;
        if (RESID) {
            float4 rr = *(const float4*)(resid + g);
            v.x += rr.x; v.y += rr.y; v.z += rr.z; v.w += rr.w;
        }
        if (WF32) *(float4*)(Cf + g) = v;
        if (WF16) {
            ((__half2*)(Ch + g))[0] = __floats2half2_rn(v.x, v.y);
            ((__half2*)(Ch + g))[1] = __floats2half2_rn(v.z, v.w);
        }
    }
}

// ---------------------------------------------------------------------------
// Raw-mma split-fp16 GEMM (fp32-accurate) with fused rope epilogue. 2-stage.
// Each stage = 4 operands x 512 chunks = 8 cp.async per thread.
// ---------------------------------------------------------------------------
#define GSR_STG_H 20480
#define GSR_SMEM 81920

__global__ void __launch_bounds__(256, 2) gemm_sr(
    const __half* __restrict__ Ah_, const __half* __restrict__ Al_,
    const __half* __restrict__ BhT, const __half* __restrict__ BlT,
    const float* __restrict__ bias,
    __half* __restrict__ Oh, __half* __restrict__ Ol,
    float extra, int M, int N, int K)
{
    extern __shared__ __align__(16) unsigned char sm[];
    __half* SH = (__half*)sm;
    __shared__ float sInv[32];

    const int tid = threadIdx.x;
    if (tid < 32)
        sInv[tid] = (float)exp(-0.28782313662425575 * (double)tid); // ln(1e4)/32

    const int warp = tid >> 5;
    const int lane = tid & 31;
    const int gid = lane >> 2;
    const int qc  = (lane & 3) * 2;
    const int wm = warp >> 1;
    const int wn = warp & 1;
    const int row0 = blockIdx.y * 128;
    const int col0 = blockIdx.x * 128;

    float acc[2][8][4];
#pragma unroll
    for (int i = 0; i < 2; i++)
#pragma unroll
        for (int t = 0; t < 8; t++)
            acc[i][t][0] = acc[i][t][1] = acc[i][t][2] = acc[i][t][3] = 0.f;

    auto load_stage = [&](int k0, int s) {
        __half* base = SH + s * GSR_STG_H;
#pragma unroll
        for (int i = 0; i < 2; i++) {
            int c = tid + i * 256;
            int r = c >> 2, q = c & 3;
            size_t ga = (size_t)(row0 + r) * K + k0 + q * 8;
            size_t gb = (size_t)(col0 + r) * K + k0 + q * 8;
            int so = r * 40 + q * 8;
            cp16(base + so,         Ah_ + ga);
            cp16(base + 5120 + so,  BhT + gb);
            cp16(base + 10240 + so, Al_ + ga);
            cp16(base + 15360 + so, BlT + gb);
        }
    };

    const int nk = K >> 5;
    load_stage(0, 0); cp_commit();
    for (int kt = 0; kt < nk; kt++) {
        cp_wait<0>();
        __syncthreads();
        if (kt + 1 < nk) { load_stage((kt + 1) << 5, (kt + 1) & 1); cp_commit(); }
        const __half* Ahs = SH + (kt & 1) * GSR_STG_H;
        const __half* Bhs = Ahs + 5120;
        const __half* Als = Ahs + 10240;
        const __half* Bls = Ahs + 15360;
#pragma unroll
        for (int kc = 0; kc < 2; kc++) {
            uint32_t ah[2][4], al[2][4];
#pragma unroll
            for (int i = 0; i < 2; i++) {
                int ao = (wm * 32 + i * 16) * 40 + kc * 16;
                ah[i][0] = *(const uint32_t*)(Ahs + ao + gid * 40 + qc);
                ah[i][1] = *(const uint32_t*)(Ahs + ao + (gid + 8) * 40 + qc);
                ah[i][2] = *(const uint32_t*)(Ahs + ao + gid * 40 + qc + 8);
                ah[i][3] = *(const uint32_t*)(Ahs + ao + (gid + 8) * 40 + qc + 8);
                al[i][0] = *(const uint32_t*)(Als + ao + gid * 40 + qc);
                al[i][1] = *(const uint32_t*)(Als + ao + (gid + 8) * 40 + qc);
                al[i][2] = *(const uint32_t*)(Als + ao + gid * 40 + qc + 8);
                al[i][3] = *(const uint32_t*)(Als + ao + (gid + 8) * 40 + qc + 8);
            }
#pragma unroll
            for (int t = 0; t < 8; t++) {
                int bo = (wn * 64 + t * 8 + gid) * 40 + kc * 16 + qc;
                uint32_t bh0 = *(const uint32_t*)(Bhs + bo);
                uint32_t bh1 = *(const uint32_t*)(Bhs + bo + 8);
                uint32_t bl0 = *(const uint32_t*)(Bls + bo);
                uint32_t bl1 = *(const uint32_t*)(Bls + bo + 8);
#pragma unroll
                for (int i = 0; i < 2; i++) {
                    mma16816(acc[i][t], ah[i], bh0, bh1);
                    mma16816(acc[i][t], ah[i], bl0, bl1);
                    mma16816(acc[i][t], al[i], bh0, bh1);
                }
            }
        }
    }
    __syncthreads();

    float* stg = (float*)sm;
#pragma unroll
    for (int i = 0; i < 2; i++)
#pragma unroll
        for (int t = 0; t < 8; t++) {
            int rb = wm * 32 + i * 16;
            int cb = wn * 64 + t * 8 + qc;
            stg[(rb + gid) * 132 + cb]     = acc[i][t][0];
            stg[(rb + gid) * 132 + cb + 1] = acc[i][t][1];
            stg[(rb + gid + 8) * 132 + cb]     = acc[i][t][2];
            stg[(rb + gid + 8) * 132 + cb + 1] = acc[i][t][3];
        }
    __syncthreads();

#pragma unroll
    for (int e = 0; e < 16; e++) {
        int idx = tid + e * 256;
        int r = idx >> 5, c4 = idx & 31;
        float t0 = stg[r * 132 + c4 * 4 + 0];
        float t1 = stg[r * 132 + c4 * 4 + 1];
        float t2 = stg[r * 132 + c4 * 4 + 2];
        float t3 = stg[r * 132 + c4 * 4 + 3];
        float4 bb = *(const float4*)(bias + col0 + c4 * 4);
        t0 += bb.x; t1 += bb.y; t2 += bb.z; t3 += bb.w;

        int gc = col0 + c4 * 4;
        int j0 = (gc & 63) >> 1;
        int row = row0 + r;
        float fs = (float)(row & (SEQ - 1));

        int ic0 = (2 * j0 < 32) ? 2 * j0 : 2 * j0 - 32;
        int is0 = (2 * j0 + 1 < 32) ? 2 * j0 + 1 : 2 * j0 - 31;
        float ca0 = fs * sInv[ic0], sa0 = fs * sInv[is0];
        float o0 = (t0 * ca0 - t1 * sa0) * extra;
        float o1 = (t0 * sa0 + t1 * ca0) * extra;

        int j1 = j0 + 1;
        int ic1 = (2 * j1 < 32) ? 2 * j1 : 2 * j1 - 32;
        int is1 = (2 * j1 + 1 < 32) ? 2 * j1 + 1 : 2 * j1 - 31;
        float ca1 = fs * sInv[ic1], sa1 = fs * sInv[is1];
        float o2 = (t2 * ca1 - t3 * sa1) * extra;
        float o3 = (t2 * sa1 + t3 * ca1) * extra;

        size_t hb = (size_t)row * N + (gc & ~63);
        __half h0 = __float2half(o0), h2v = __float2half(o2);
        __half h1 = __float2half(o1), h3v = __float2half(o3);
        *(__half2*)(Oh + hb + j0)      = __halves2half2(h0, h2v);
        *(__half2*)(Oh + hb + 32 + j0) = __halves2half2(h1, h3v);
        *(__half2*)(Ol + hb + j0)      = __floats2half2_rn(o0 - __half2float(h0),
                                                           o2 - __half2float(h2v));
        *(__half2*)(Ol + hb + 32 + j0) = __floats2half2_rn(o1 - __half2float(h1),
                                                           o3 - __half2float(h3v));
    }
}

// ---------------------------------------------------------------------------
// FA2-style flash attention (unchanged from R12)
// ---------------------------------------------------------------------------
#define ATT_SMEM 55296

__global__ void __launch_bounds__(128, 3) attn_kernel(
    const __half* __restrict__ qh, const __half* __restrict__ ql,
    const __half* __restrict__ kh, const __half* __restrict__ kl,
    const __half* __restrict__ v, __half* __restrict__ ctx)
{
    extern __shared__ __align__(16) unsigned char sm[];
    __half* KH = (__half*)sm;
    __half* KL = KH + 9216;
    __half* VT = KL + 9216;

    const int tid = threadIdx.x;
    const int w = tid >> 5;
    const int lane = tid & 31;
    const int gid = lane >> 2;
    const int qc  = (lane & 3) * 2;
    const int qt = blockIdx.x;
    const int h = blockIdx.y;
    const int b = blockIdx.z;
    const int hc = h * DHEAD;
    const int brow = b * SEQ;
    const int qrow0 = brow + qt * 64 + w * 16;

    uint32_t qAh[4][4], qAl[4][4];
#pragma unroll
    for (int kc = 0; kc < 4; kc++) {
        const __half* bh = qh + (size_t)qrow0 * DMODEL + hc + kc * 16;
        const __half* bl = ql + (size_t)qrow0 * DMODEL + hc + kc * 16;
        qAh[kc][0] = *(const uint32_t*)(bh + (size_t)gid * DMODEL + qc);
        qAh[kc][1] = *(const uint32_t*)(bh + (size_t)(gid + 8) * DMODEL + qc);
        qAh[kc][2] = *(const uint32_t*)(bh + (size_t)gid * DMODEL + qc + 8);
        qAh[kc][3] = *(const uint32_t*)(bh + (size_t)(gid + 8) * DMODEL + qc + 8);
        qAl[kc][0] = *(const uint32_t*)(bl + (size_t)gid * DMODEL + qc);
        qAl[kc][1] = *(const uint32_t*)(bl + (size_t)(gid + 8) * DMODEL + qc);
        qAl[kc][2] = *(const uint32_t*)(bl + (size_t)gid * DMODEL + qc + 8);
        qAl[kc][3] = *(const uint32_t*)(bl + (size_t)(gid + 8) * DMODEL + qc + 8);
    }

    float O[8][4];
#pragma unroll
    for (int t = 0; t < 8; t++)
        O[t][0] = O[t][1] = O[t][2] = O[t][3] = 0.f;
    float m0 = -1e30f, m1 = -1e30f, l0 = 0.f, l1 = 0.f;

    auto load_stage = [&](int kv, int s) {
#pragma unroll
        for (int i = 0; i < 4; i++) {
            int c = tid + i * 128;
            int rr = c >> 3, qq = c & 7;
            size_t g = (size_t)(brow + kv * 64 + rr) * DMODEL + hc + qq * 8;
            int so = s * 4608 + rr * 72 + qq * 8;
            cp16(KH + so, kh + g);
            cp16(KL + so, kl + g);
            cp16(VT + so, v + g);
        }
    };

    const int NT = SEQ / 64;
    load_stage(0, 0); cp_commit();

    for (int kt = 0; kt < NT; kt++) {
        cp_wait<0>();
        __syncthreads();
        if (kt + 1 < NT) { load_stage(kt + 1, (kt + 1) & 1); cp_commit(); }

        const int s = kt & 1;
        const __half* KHs = KH + s * 4608;
        const __half* KLs = KL + s * 4608;
        const __half* VTs = VT + s * 4608;

        float S[8][4];
#pragma unroll
        for (int t = 0; t < 8; t++) {
            S[t][0] = S[t][1] = S[t][2] = S[t][3] = 0.f;
#pragma unroll
            for (int kc = 0; kc < 4; kc++) {
                int koff = (t * 8 + gid) * 72 + kc * 16 + qc;
                uint32_t bh0 = *(const uint32_t*)(KHs + koff);
                uint32_t bh1 = *(const uint32_t*)(KHs + koff + 8);
                uint32_t bl0 = *(const uint32_t*)(KLs + koff);
                uint32_t bl1 = *(const uint32_t*)(KLs + koff + 8);
                mma16816(S[t], qAh[kc], bh0, bh1);
                mma16816(S[t], qAh[kc], bl0, bl1);
                mma16816(S[t], qAl[kc], bh0, bh1);
            }
        }

        float mt0 = -1e30f, mt1 = -1e30f;
#pragma unroll
        for (int t = 0; t < 8; t++) {
            mt0 = fmaxf(mt0, fmaxf(S[t][0], S[t][1]));
            mt1 = fmaxf(mt1, fmaxf(S[t][2], S[t][3]));
        }
        mt0 = fmaxf(mt0, __shfl_xor_sync(0xffffffffu, mt0, 1));
        mt0 = fmaxf(mt0, __shfl_xor_sync(0xffffffffu, mt0, 2));
        mt1 = fmaxf(mt1, __shfl_xor_sync(0xffffffffu, mt1, 1));
        mt1 = fmaxf(mt1, __shfl_xor_sync(0xffffffffu, mt1, 2));
        float mn0 = fmaxf(m0, mt0), mn1 = fmaxf(m1, mt1);
        float al0 = __expf(m0 - mn0), al1 = __expf(m1 - mn1);

        uint32_t pA[4][4];
        float ls0 = 0.f, ls1 = 0.f;
#pragma unroll
        for (int t = 0; t < 8; t++) {
            float p0 = __expf(S[t][0] - mn0);
            float p1 = __expf(S[t][1] - mn0);
            float p2 = __expf(S[t][2] - mn1);
            float p3 = __expf(S[t][3] - mn1);
            ls0 += p0 + p1;
            ls1 += p2 + p3;
            pA[t >> 1][(t & 1) * 2 + 0] = f2u2(p0, p1);
            pA[t >> 1][(t & 1) * 2 + 1] = f2u2(p2, p3);
        }
        ls0 += __shfl_xor_sync(0xffffffffu, ls0, 1);
        ls0 += __shfl_xor_sync(0xffffffffu, ls0, 2);
        ls1 += __shfl_xor_sync(0xffffffffu, ls1, 1);
        ls1 += __shfl_xor_sync(0xffffffffu, ls1, 2);
        l0 = l0 * al0 + ls0;
        l1 = l1 * al1 + ls1;
        m0 = mn0; m1 = mn1;
#pragma unroll
        for (int t = 0; t < 8; t++) {
            O[t][0] *= al0; O[t][1] *= al0;
            O[t][2] *= al1; O[t][3] *= al1;
        }

#pragma unroll
        for (int t = 0; t < 8; t++) {
#pragma unroll
            for (int kc = 0; kc < 4; kc++) {
                int vr = (kc * 16 + qc) * 72 + t * 8 + gid;
                __half x0 = VTs[vr];
                __half x1 = VTs[vr + 72];
                __half x2 = VTs[vr + 8 * 72];
                __half x3 = VTs[vr + 9 * 72];
                mma16816(O[t], pA[kc], h2u(x0, x1), h2u(x2, x3));
            }
        }
    }

    float inv0 = 1.f / l0, inv1 = 1.f / l1;
#pragma unroll
    for (int t = 0; t < 8; t++) {
        *(__half2*)(ctx + (size_t)(qrow0 + gid) * DMODEL + hc + t * 8 + qc) =
            __floats2half2_rn(O[t][0] * inv0, O[t][1] * inv0);
        *(__half2*)(ctx + (size_t)(qrow0 + gid + 8) * DMODEL + hc + t * 8 + qc) =
            __floats2half2_rn(O[t][2] * inv1, O[t][3] * inv1);
    }
}

// ---------------------------------------------------------------------------
// LayerNorm (unchanged)
// ---------------------------------------------------------------------------
__global__ void __launch_bounds__(256) ln_kernel(
    const float* __restrict__ in, const float* __restrict__ g,
    const float* __restrict__ be, float* __restrict__ outf,
    __half* __restrict__ outh)
{
    int row = blockIdx.x;
    int tid = threadIdx.x;
    float4 v = ((const float4*)(in + (size_t)row * DMODEL))[tid];
    float s  = v.x + v.y + v.z + v.w;
    float ss = v.x * v.x + v.y * v.y + v.z * v.z + v.w * v.w;
#pragma unroll
    for (int o = 16; o > 0; o >>= 1) {
        s  += __shfl_down_sync(0xffffffffu, s, o);
        ss += __shfl_down_sync(0xffffffffu, ss, o);
    }
    __shared__ float shs[8], shss[8], smu, srs;
    int lane = tid & 31, wid = tid >> 5;
    if (lane == 0) { shs[wid] = s; shss[wid] = ss; }
    __syncthreads();
    if (tid == 0) {
        float S = 0.f, SS = 0.f;
#pragma unroll
        for (int i = 0; i < 8; i++) { S += shs[i]; SS += shss[i]; }
        float mu = S * (1.f / 1024.f);
        float var = SS * (1.f / 1024.f) - mu * mu;
        smu = mu;
        srs = rsqrtf(var + 1e-5f);
    }
    __syncthreads();
    float mu = smu, rs = srs;
    float4 gv = ((const float4*)g)[tid];
    float4 bv = ((const float4*)be)[tid];
    float4 o;
    o.x = (v.x - mu) * rs * gv.x + bv.x;
    o.y = (v.y - mu) * rs * gv.y + bv.y;
    o.z = (v.z - mu) * rs * gv.z + bv.z;
    o.w = (v.w - mu) * rs * gv.w + bv.w;
    ((float4*)(outf + (size_t)row * DMODEL))[tid] = o;
    if (outh) {
        ((__half2*)(outh + (size_t)row * DMODEL))[2 * tid]     = __floats2half2_rn(o.x, o.y);
        ((__half2*)(outh + (size_t)row * DMODEL))[2 * tid + 1] = __floats2half2_rn(o.z, o.w);
    }
}

extern "C" void kernel_launch(void* const* d_in, const int* in_sizes, int n_in,
                              void* d_out, int out_size) {
    const float* x   = (const float*)d_in[0];
    const float* wq  = (const float*)d_in[1];
    const float* bq  = (const float*)d_in[2];
    const float* wk  = (const float*)d_in[3];
    const float* bk  = (const float*)d_in[4];
    const float* wv  = (const float*)d_in[5];
    const float* bv  = (const float*)d_in[6];
    const float* wo  = (const float*)d_in[7];
    const float* bo  = (const float*)d_in[8];
    const float* w1  = (const float*)d_in[9];
    const float* b1  = (const float*)d_in[10];
    const float* w2  = (const float*)d_in[11];
    const float* b2  = (const float*)d_in[12];
    const float* g1  = (const float*)d_in[13];
    const float* be1 = (const float*)d_in[14];
    const float* g2  = (const float*)d_in[15];
    const float* be2 = (const float*)d_in[16];
    float* out = (float*)d_out;

    void *p;
    cudaGetSymbolAddress(&p, g_xh);    __half* xh   = (__half*)p;
    cudaGetSymbolAddress(&p, g_xl);    __half* xl   = (__half*)p;
    cudaGetSymbolAddress(&p, g_wqTh);  __half* wqTh = (__half*)p;
    cudaGetSymbolAddress(&p, g_wqTl);  __half* wqTl = (__half*)p;
    cudaGetSymbolAddress(&p, g_wkTh);  __half* wkTh = (__half*)p;
    cudaGetSymbolAddress(&p, g_wkTl);  __half* wkTl = (__half*)p;
    cudaGetSymbolAddress(&p, g_wvT);   __half* wvT  = (__half*)p;
    cudaGetSymbolAddress(&p, g_woT);   __half* woT  = (__half*)p;
    cudaGetSymbolAddress(&p, g_w1T);   __half* w1T  = (__half*)p;
    cudaGetSymbolAddress(&p, g_w2T);   __half* w2T  = (__half*)p;
    cudaGetSymbolAddress(&p, g_qrh);   __half* qrh  = (__half*)p;
    cudaGetSymbolAddress(&p, g_qrl);   __half* qrl  = (__half*)p;
    cudaGetSymbolAddress(&p, g_krh);   __half* krh  = (__half*)p;
    cudaGetSymbolAddress(&p, g_krl);   __half* krl  = (__half*)p;
    cudaGetSymbolAddress(&p, g_vh);    __half* vh   = (__half*)p;
    cudaGetSymbolAddress(&p, g_ctx);   __half* ctx  = (__half*)p;
    cudaGetSymbolAddress(&p, g_res1);  float*  res1 = (float*)p;
    cudaGetSymbolAddress(&p, g_hbuf);  float*  hbuf = (float*)p;
    cudaGetSymbolAddress(&p, g_hh);    __half* hh   = (__half*)p;
    cudaGetSymbolAddress(&p, g_ff1);   __half* ff1  = (__half*)p;
    cudaGetSymbolAddress(&p, g_res2);  float*  res2 = (float*)p;

    cudaFuncSetAttribute(gemm_r<false, false, false, true>,
                         cudaFuncAttributeMaxDynamicSharedMemorySize, GR_SMEM);
    cudaFuncSetAttribute(gemm_r<false, true, true, false>,
                         cudaFuncAttributeMaxDynamicSharedMemorySize, GR_SMEM);
    cudaFuncSetAttribute(gemm_r<true, false, false, true>,
                         cudaFuncAttributeMaxDynamicSharedMemorySize, GR_SMEM);
    cudaFuncSetAttribute(gemm_sr,
                         cudaFuncAttributeMaxDynamicSharedMemorySize, GSR_SMEM);
    cudaFuncSetAttribute(attn_kernel,
                         cudaFuncAttributeMaxDynamicSharedMemorySize, ATT_SMEM);

    // 0: x hi/lo split
    convx_kernel<<<(X4 + 255) / 256, 256>>>(x, xh, xl);
    // 1-4: attention-block weight transposes
    dim3 tg1(DMODEL / 32, DMODEL / 32);
    tconv_split<<<tg1, 256>>>(wq, wqTh, wqTl, DMODEL, DMODEL);
    tconv_split<<<tg1, 256>>>(wk, wkTh, wkTl, DMODEL, DMODEL);
    tconv_plain<<<tg1, 256>>>(wv, wvT, DMODEL, DMODEL);
    tconv_plain<<<tg1, 256>>>(wo, woT, DMODEL, DMODEL);

    dim3 grid1(DMODEL / 128, ROWS / 128);   // (8, 64)
    dim3 gridF(DFF / 128,    ROWS / 128);   // (32, 64)

    // 5: Q projection (split + rope)  <- ncu capture slot
    gemm_sr<<<grid1, 256, GSR_SMEM>>>(xh, xl, wqTh, wqTl, bq, qrh, qrl, 0.125f, ROWS, DMODEL, DMODEL);
    // 6: K projection (split + rope)
    gemm_sr<<<grid1, 256, GSR_SMEM>>>(xh, xl, wkTh, wkTl, bk, krh, krl, 1.0f, ROWS, DMODEL, DMODEL);
    // 7: V projection (plain, fp16 out)
    gemm_r<false, false, false, true><<<grid1, 256, GR_SMEM>>>(
        xh, wvT, bv, nullptr, nullptr, vh, ROWS, DMODEL, DMODEL);
    // 8: attention
    attn_kernel<<<dim3(SEQ / 64, NHEADS, BATCH), 128, ATT_SMEM>>>(qrh, qrl, krh, krl, vh, ctx);
    // 9: output projection + residual(x)
    gemm_r<false, true, true, false><<<grid1, 256, GR_SMEM>>>(
        ctx, woT, bo, x, res1, nullptr, ROWS, DMODEL, DMODEL);
    // 10: LN1
    ln_kernel<<<ROWS, 256>>>(res1, g1, be1, hbuf, hh);
    // 11-12: FFN weight transposes
    tconv_plain<<<dim3(DFF / 32, DMODEL / 32), 256>>>(w1, w1T, DMODEL, DFF);
    tconv_plain<<<dim3(DMODEL / 32, DFF / 32), 256>>>(w2, w2T, DFF, DMODEL);
    // 13: FFN1 (relu, fp16 out)
    gemm_r<true, false, false, true><<<gridF, 256, GR_SMEM>>>(
        hh, w1T, b1, nullptr, nullptr, ff1, ROWS, DFF, DMODEL);
    // 14: FFN2 (+resid hbuf, fp32 out)
    gemm_r<false, true, true, false><<<grid1, 256, GR_SMEM>>>(
        ff1, w2T, b2, hbuf, res2, nullptr, ROWS, DMODEL, DFF);
    // 15: LN2 -> output
    ln_kernel<<<ROWS, 256>>>(res2, g2, be2, out, nullptr);
}

// round 17
// speedup vs baseline: 1.2005x; 1.2005x over previous
#include <cuda_runtime.h>
#include <cuda_fp16.h>
#include <cstdint>

// ---------------------------------------------------------------------------
#define BATCH 4
#define SEQ 2048
#define ROWS (BATCH * SEQ)       // 8192
#define DMODEL 1024
#define NHEADS 16
#define DHEAD 64
#define DFF 4096

// ---------------------------------------------------------------------------
// Scratch (static device globals; no allocation allowed)
// ---------------------------------------------------------------------------
__device__ __half g_xh[ROWS * DMODEL];
__device__ __half g_xl[ROWS * DMODEL];
__device__ __half g_wqTh[DMODEL * DMODEL];   // [N,K] hi
__device__ __half g_wqTl[DMODEL * DMODEL];
__device__ __half g_wkTh[DMODEL * DMODEL];
__device__ __half g_wkTl[DMODEL * DMODEL];
__device__ __half g_wvT[DMODEL * DMODEL];
__device__ __half g_woT[DMODEL * DMODEL];
__device__ __half g_w1T[DMODEL * DFF];       // [DFF, DMODEL]
__device__ __half g_w2T[DFF * DMODEL];       // [DMODEL, DFF]

__device__ __half g_qrh[ROWS * DMODEL];
__device__ __half g_qrl[ROWS * DMODEL];
__device__ __half g_krh[ROWS * DMODEL];
__device__ __half g_krl[ROWS * DMODEL];
__device__ __half g_vh[ROWS * DMODEL];
__device__ __half g_ctx[ROWS * DMODEL];
__device__ float  g_res1[ROWS * DMODEL];
__device__ float  g_hbuf[ROWS * DMODEL];
__device__ __half g_hh[ROWS * DMODEL];
__device__ __half g_ff1[ROWS * DFF];
__device__ float  g_res2[ROWS * DMODEL];

// ---------------------------------------------------------------------------
// cp.async + mma + ldmatrix helpers
// ---------------------------------------------------------------------------
__device__ __forceinline__ void cp16(void* s, const void* g) {
    unsigned int sa = (unsigned int)__cvta_generic_to_shared(s);
    asm volatile("cp.async.cg.shared.global [%0], [%1], 16;\n" :: "r"(sa), "l"(g) : "memory");
}
__device__ __forceinline__ void cp16u(unsigned int sa, const void* g) {
    asm volatile("cp.async.cg.shared.global [%0], [%1], 16;\n" :: "r"(sa), "l"(g) : "memory");
}
__device__ __forceinline__ void cp_commit() {
    asm volatile("cp.async.commit_group;\n" ::: "memory");
}
template<int N> __device__ __forceinline__ void cp_wait() {
    asm volatile("cp.async.wait_group %0;\n" :: "n"(N) : "memory");
}

__device__ __forceinline__ void mma16816(float* c, const uint32_t* a,
                                         uint32_t b0, uint32_t b1) {
    asm volatile(
        "mma.sync.aligned.m16n8k16.row.col.f32.f16.f16.f32 "
        "{%0,%1,%2,%3}, {%4,%5,%6,%7}, {%8,%9}, {%0,%1,%2,%3};\n"
        : "+f"(c[0]), "+f"(c[1]), "+f"(c[2]), "+f"(c[3])
        : "r"(a[0]), "r"(a[1]), "r"(a[2]), "r"(a[3]), "r"(b0), "r"(b1));
}
__device__ __forceinline__ void ldsm4(uint32_t* r, unsigned int saddr) {
    asm volatile("ldmatrix.sync.aligned.m8n8.x4.shared.b16 {%0,%1,%2,%3}, [%4];"
        : "=r"(r[0]), "=r"(r[1]), "=r"(r[2]), "=r"(r[3]) : "r"(saddr));
}
__device__ __forceinline__ uint32_t h2u(__half a, __half b) {
    __half2 t = __halves2half2(a, b);
    return *(uint32_t*)&t;
}
__device__ __forceinline__ uint32_t f2u2(float a, float b) {
    __half2 t = __floats2half2_rn(a, b);
    return *(uint32_t*)&t;
}

// ---------------------------------------------------------------------------
// x conversion (hi/lo split), tiled transpose-convert for weights
// ---------------------------------------------------------------------------
#define X4 (ROWS * DMODEL / 4)

__global__ void __launch_bounds__(256) convx_kernel(const float* __restrict__ in,
                                                    __half* __restrict__ hi,
                                                    __half* __restrict__ lo) {
    int i = blockIdx.x * 256 + threadIdx.x;
    if (i < X4) {
        float4 v = ((const float4*)in)[i];
        __half hx = __float2half(v.x), hy = __float2half(v.y);
        __half hz = __float2half(v.z), hw = __float2half(v.w);
        ((__half2*)hi)[2 * i]     = __halves2half2(hx, hy);
        ((__half2*)hi)[2 * i + 1] = __halves2half2(hz, hw);
        ((__half2*)lo)[2 * i]     = __floats2half2_rn(v.x - __half2float(hx),
                                                      v.y - __half2float(hy));
        ((__half2*)lo)[2 * i + 1] = __floats2half2_rn(v.z - __half2float(hz),
                                                      v.w - __half2float(hw));
    }
}

__global__ void __launch_bounds__(256) tconv_plain(const float* __restrict__ w,
                                                   __half* __restrict__ wT,
                                                   int K, int N) {
    __shared__ float t[32][33];
    int n0 = blockIdx.x * 32, k0 = blockIdx.y * 32;
    int tx = threadIdx.x & 31, ty = threadIdx.x >> 5;
#pragma unroll
    for (int i = 0; i < 4; i++)
        t[ty + i * 8][tx] = w[(size_t)(k0 + ty + i * 8) * N + n0 + tx];
    __syncthreads();
#pragma unroll
    for (int i = 0; i < 4; i++)
        wT[(size_t)(n0 + ty + i * 8) * K + k0 + tx] = __float2half(t[tx][ty + i * 8]);
}

__global__ void __launch_bounds__(256) tconv_split(const float* __restrict__ w,
                                                   __half* __restrict__ hiT,
                                                   __half* __restrict__ loT,
                                                   int K, int N) {
    __shared__ float t[32][33];
    int n0 = blockIdx.x * 32, k0 = blockIdx.y * 32;
    int tx = threadIdx.x & 31, ty = threadIdx.x >> 5;
#pragma unroll
    for (int i = 0; i < 4; i++)
        t[ty + i * 8][tx] = w[(size_t)(k0 + ty + i * 8) * N + n0 + tx];
    __syncthreads();
#pragma unroll
    for (int i = 0; i < 4; i++) {
        float v = t[tx][ty + i * 8];
        __half h = __float2half(v);
        size_t o = (size_t)(n0 + ty + i * 8) * K + k0 + tx;
        hiT[o] = h;
        loT[o] = __float2half(v - __half2float(h));
    }
}

// ---------------------------------------------------------------------------
// Swizzled-LDSM plain fp16 GEMM: C = A[M,K] @ BT[N,K]^T + bias (+epilogues).
// 128x128x32 tiles, 8 warps (4x2), warp tile 32x64.
// Smem rows of 32 halfs (64B), chunk swizzle q ^ ((r>>1)&3) -> ldmatrix
// conflict-free. Fragments via ldmatrix.x4 (lane map == verified per-lane).
// Acc chain order == wmma kernels -> bit-identical output.
// Stage = A 8192B + B 8192B = 16384; x3 = 49152. Epilogue 67584 -> GR_SMEM.
// ---------------------------------------------------------------------------
#define GR_STG 16384
#define GR_SMEM 67584

template<bool RELU, bool RESID, bool WF32, bool WF16>
__global__ void __launch_bounds__(256) gemm_r(
    const __half* __restrict__ A, const __half* __restrict__ BT,
    const float* __restrict__ bias, const float* __restrict__ resid,
    float* __restrict__ Cf, __half* __restrict__ Ch,
    int M, int N, int K)
{
    extern __shared__ __align__(16) unsigned char sm[];
    const unsigned int sbase = (unsigned int)__cvta_generic_to_shared(sm);

    const int tid = threadIdx.x;
    const int warp = tid >> 5;
    const int lane = tid & 31;
    const int gid = lane >> 2;
    const int qc  = (lane & 3) * 2;
    const int wm = warp >> 1;
    const int wn = warp & 1;
    const int row0 = blockIdx.y * 128;
    const int col0 = blockIdx.x * 128;

    // ldmatrix per-lane address components
    const int aro = (lane & 7) + ((lane >> 3) & 1) * 8;  // A row offset 0..15
    const int acs = (lane >> 4) & 1;                     // A chunk select
    const int bro = (lane & 7);                          // B row within n8
    const int bts = (lane >> 4) & 1;                     // B tile select (t / t+1)
    const int bcs = (lane >> 3) & 1;                     // B chunk select

    float acc[2][8][4];
#pragma unroll
    for (int i = 0; i < 2; i++)
#pragma unroll
        for (int t = 0; t < 8; t++)
            acc[i][t][0] = acc[i][t][1] = acc[i][t][2] = acc[i][t][3] = 0.f;

    auto load_stage = [&](int k0, int s) {
        unsigned int base = sbase + s * GR_STG;
#pragma unroll
        for (int i = 0; i < 2; i++) {          // A: 512 chunks
            int c = tid + i * 256;
            int r = c >> 2, q = c & 3;
            int sw = q ^ ((r >> 1) & 3);
            cp16u(base + r * 64 + sw * 16, A + (size_t)(row0 + r) * K + k0 + q * 8);
        }
#pragma unroll
        for (int i = 0; i < 2; i++) {          // B: 512 chunks
            int c = tid + i * 256;
            int r = c >> 2, q = c & 3;
            int sw = q ^ ((r >> 1) & 3);
            cp16u(base + 8192 + r * 64 + sw * 16, BT + (size_t)(col0 + r) * K + k0 + q * 8);
        }
    };

    const int nk = K >> 5;
    load_stage(0, 0); cp_commit();
    load_stage(32, 1); cp_commit();
    for (int kt = 0; kt < nk; kt++) {
        if (kt + 1 < nk) cp_wait<1>(); else cp_wait<0>();
        __syncthreads();
        if (kt + 2 < nk) { load_stage((kt + 2) << 5, (kt + 2) % 3); cp_commit(); }
        unsigned int As = sbase + (kt % 3) * GR_STG;
        unsigned int Bs = As + 8192;
#pragma unroll
        for (int kc = 0; kc < 2; kc++) {
            uint32_t a[2][4];
#pragma unroll
            for (int i = 0; i < 2; i++) {
                int r = wm * 32 + i * 16 + aro;
                int cch = kc * 2 + acs;
                int sw = cch ^ ((r >> 1) & 3);
                ldsm4(a[i], As + r * 64 + sw * 16);
            }
#pragma unroll
            for (int tp = 0; tp < 4; tp++) {
                int t0 = tp * 2;
                int r = wn * 64 + (t0 + bts) * 8 + bro;
                int cch = kc * 2 + bcs;
                int sw = cch ^ ((r >> 1) & 3);
                uint32_t b4[4];
                ldsm4(b4, Bs + r * 64 + sw * 16);
#pragma unroll
                for (int tt = 0; tt < 2; tt++)
#pragma unroll
                    for (int i = 0; i < 2; i++)
                        mma16816(acc[i][t0 + tt], a[i], b4[tt * 2], b4[tt * 2 + 1]);
            }
        }
    }
    __syncthreads();

    float* stg = (float*)sm;
#pragma unroll
    for (int i = 0; i < 2; i++)
#pragma unroll
        for (int t = 0; t < 8; t++) {
            int rb = wm * 32 + i * 16;
            int cb = wn * 64 + t * 8 + qc;
            stg[(rb + gid) * 132 + cb]     = acc[i][t][0];
            stg[(rb + gid) * 132 + cb + 1] = acc[i][t][1];
            stg[(rb + gid + 8) * 132 + cb]     = acc[i][t][2];
            stg[(rb + gid + 8) * 132 + cb + 1] = acc[i][t][3];
        }
    __syncthreads();

#pragma unroll
    for (int e = 0; e < 16; e++) {
        int idx = tid + e * 256;
        int r = idx >> 5, c4 = idx & 31;
        float4 v;
        v.x = stg[r * 132 + c4 * 4 + 0];
        v.y = stg[r * 132 + c4 * 4 + 1];
        v.z = stg[r * 132 + c4 * 4 + 2];
        v.w = stg[r * 132 + c4 * 4 + 3];
        float4 bb = *(const float4*)(bias + col0 + c4 * 4);
        v.x += bb.x; v.y += bb.y; v.z += bb.z; v.w += bb.w;
        if (RELU) { v.x = fmaxf(v.x, 0.f); v.y = fmaxf(v.y, 0.f); v.z = fmaxf(v.z, 0.f); v.w = fmaxf(v.w, 0.f); }
        size_t g = (size_t)(row0 + r) * N + col0 + c4 * 4;
        if (RESID) {
            float4 rr = *(const float4*)(resid + g);
            v.x += rr.x; v.y += rr.y; v.z += rr.z; v.w += rr.w;
        }
        if (WF32) *(float4*)(Cf + g) = v;
        if (WF16) {
            ((__half2*)(Ch + g))[0] = __floats2half2_rn(v.x, v.y);
            ((__half2*)(Ch + g))[1] = __floats2half2_rn(v.z, v.w);
        }
    }
}

// ---------------------------------------------------------------------------
// Swizzled-LDSM split-fp16 GEMM (fp32-accurate) + fused rope. 2-stage.
// Stage = 4 x 8192B = 32768; x2 = 65536. Epilogue 67584 -> GSR_SMEM.
// ---------------------------------------------------------------------------
#define GSR_STG 32768
#define GSR_SMEM 67584

__global__ void __launch_bounds__(256, 2) gemm_sr(
    const __half* __restrict__ Ah_, const __half* __restrict__ Al_,
    const __half* __restrict__ BhT, const __half* __restrict__ BlT,
    const float* __restrict__ bias,
    __half* __restrict__ Oh, __half* __restrict__ Ol,
    float extra, int M, int N, int K)
{
    extern __shared__ __align__(16) unsigned char sm[];
    const unsigned int sbase = (unsigned int)__cvta_generic_to_shared(sm);
    __shared__ float sInv[32];

    const int tid = threadIdx.x;
    if (tid < 32)
        sInv[tid] = (float)exp(-0.28782313662425575 * (double)tid); // ln(1e4)/32

    const int warp = tid >> 5;
    const int lane = tid & 31;
    const int gid = lane >> 2;
    const int qc  = (lane & 3) * 2;
    const int wm = warp >> 1;
    const int wn = warp & 1;
    const int row0 = blockIdx.y * 128;
    const int col0 = blockIdx.x * 128;

    const int aro = (lane & 7) + ((lane >> 3) & 1) * 8;
    const int acs = (lane >> 4) & 1;
    const int bro = (lane & 7);
    const int bts = (lane >> 4) & 1;
    const int bcs = (lane >> 3) & 1;

    float acc[2][8][4];
#pragma unroll
    for (int i = 0; i < 2; i++)
#pragma unroll
        for (int t = 0; t < 8; t++)
            acc[i][t][0] = acc[i][t][1] = acc[i][t][2] = acc[i][t][3] = 0.f;

    auto load_stage = [&](int k0, int s) {
        unsigned int base = sbase + s * GSR_STG;
#pragma unroll
        for (int i = 0; i < 2; i++) {
            int c = tid + i * 256;
            int r = c >> 2, q = c & 3;
            int sw = q ^ ((r >> 1) & 3);
            size_t ga = (size_t)(row0 + r) * K + k0 + q * 8;
            size_t gb = (size_t)(col0 + r) * K + k0 + q * 8;
            unsigned int so = r * 64 + sw * 16;
            cp16u(base + so,         Ah_ + ga);
            cp16u(base + 8192 + so,  BhT + gb);
            cp16u(base + 16384 + so, Al_ + ga);
            cp16u(base + 24576 + so, BlT + gb);
        }
    };

    const int nk = K >> 5;
    load_stage(0, 0); cp_commit();
    for (int kt = 0; kt < nk; kt++) {
        cp_wait<0>();
        __syncthreads();
        if (kt + 1 < nk) { load_stage((kt + 1) << 5, (kt + 1) & 1); cp_commit(); }
        unsigned int Ahs = sbase + (kt & 1) * GSR_STG;
        unsigned int Bhs = Ahs + 8192;
        unsigned int Als = Ahs + 16384;
        unsigned int Bls = Ahs + 24576;
#pragma unroll
        for (int kc = 0; kc < 2; kc++) {
            uint32_t ah[2][4], al[2][4];
#pragma unroll
            for (int i = 0; i < 2; i++) {
                int r = wm * 32 + i * 16 + aro;
                int cch = kc * 2 + acs;
                int sw = cch ^ ((r >> 1) & 3);
                ldsm4(ah[i], Ahs + r * 64 + sw * 16);
                ldsm4(al[i], Als + r * 64 + sw * 16);
            }
#pragma unroll
            for (int tp = 0; tp < 4; tp++) {
                int t0 = tp * 2;
                int r = wn * 64 + (t0 + bts) * 8 + bro;
                int cch = kc * 2 + bcs;
                int sw = cch ^ ((r >> 1) & 3);
                uint32_t bh4[4], bl4[4];
                ldsm4(bh4, Bhs + r * 64 + sw * 16);
                ldsm4(bl4, Bls + r * 64 + sw * 16);
#pragma unroll
                for (int tt = 0; tt < 2; tt++)
#pragma unroll
                    for (int i = 0; i < 2; i++) {
                        mma16816(acc[i][t0 + tt], ah[i], bh4[tt * 2], bh4[tt * 2 + 1]);
                        mma16816(acc[i][t0 + tt], ah[i], bl4[tt * 2], bl4[tt * 2 + 1]);
                        mma16816(acc[i][t0 + tt], al[i], bh4[tt * 2], bh4[tt * 2 + 1]);
                    }
            }
        }
    }
    __syncthreads();

    float* stg = (float*)sm;
#pragma unroll
    for (int i = 0; i < 2; i++)
#pragma unroll
        for (int t = 0; t < 8; t++) {
            int rb = wm * 32 + i * 16;
            int cb = wn * 64 + t * 8 + qc;
            stg[(rb + gid) * 132 + cb]     = acc[i][t][0];
            stg[(rb + gid) * 132 + cb + 1] = acc[i][t][1];
            stg[(rb + gid + 8) * 132 + cb]     = acc[i][t][2];
            stg[(rb + gid + 8) * 132 + cb + 1] = acc[i][t][3];
        }
    __syncthreads();

#pragma unroll
    for (int e = 0; e < 16; e++) {
        int idx = tid + e * 256;
        int r = idx >> 5, c4 = idx & 31;
        float t0 = stg[r * 132 + c4 * 4 + 0];
        float t1 = stg[r * 132 + c4 * 4 + 1];
        float t2 = stg[r * 132 + c4 * 4 + 2];
        float t3 = stg[r * 132 + c4 * 4 + 3];
        float4 bb = *(const float4*)(bias + col0 + c4 * 4);
        t0 += bb.x; t1 += bb.y; t2 += bb.z; t3 += bb.w;

        int gc = col0 + c4 * 4;
        int j0 = (gc & 63) >> 1;
        int row = row0 + r;
        float fs = (float)(row & (SEQ - 1));

        int ic0 = (2 * j0 < 32) ? 2 * j0 : 2 * j0 - 32;
        int is0 = (2 * j0 + 1 < 32) ? 2 * j0 + 1 : 2 * j0 - 31;
        float ca0 = fs * sInv[ic0], sa0 = fs * sInv[is0];
        float o0 = (t0 * ca0 - t1 * sa0) * extra;
        float o1 = (t0 * sa0 + t1 * ca0) * extra;

        int j1 = j0 + 1;
        int ic1 = (2 * j1 < 32) ? 2 * j1 : 2 * j1 - 32;
        int is1 = (2 * j1 + 1 < 32) ? 2 * j1 + 1 : 2 * j1 - 31;
        float ca1 = fs * sInv[ic1], sa1 = fs * sInv[is1];
        float o2 = (t2 * ca1 - t3 * sa1) * extra;
        float o3 = (t2 * sa1 + t3 * ca1) * extra;

        size_t hb = (size_t)row * N + (gc & ~63);
        __half h0 = __float2half(o0), h2v = __float2half(o2);
        __half h1 = __float2half(o1), h3v = __float2half(o3);
        *(__half2*)(Oh + hb + j0)      = __halves2half2(h0, h2v);
        *(__half2*)(Oh + hb + 32 + j0) = __halves2half2(h1, h3v);
        *(__half2*)(Ol + hb + j0)      = __floats2half2_rn(o0 - __half2float(h0),
                                                           o2 - __half2float(h2v));
        *(__half2*)(Ol + hb + 32 + j0) = __floats2half2_rn(o1 - __half2float(h1),
                                                           o3 - __half2float(h3v));
    }
}

// ---------------------------------------------------------------------------
// FA2-style flash attention (unchanged, proven)
// ---------------------------------------------------------------------------
#define ATT_SMEM 55296

__global__ void __launch_bounds__(128, 3) attn_kernel(
    const __half* __restrict__ qh, const __half* __restrict__ ql,
    const __half* __restrict__ kh, const __half* __restrict__ kl,
    const __half* __restrict__ v, __half* __restrict__ ctx)
{
    extern __shared__ __align__(16) unsigned char sm[];
    __half* KH = (__half*)sm;
    __half* KL = KH + 9216;
    __half* VT = KL + 9216;

    const int tid = threadIdx.x;
    const int w = tid >> 5;
    const int lane = tid & 31;
    const int gid = lane >> 2;
    const int qc  = (lane & 3) * 2;
    const int qt = blockIdx.x;
    const int h = blockIdx.y;
    const int b = blockIdx.z;
    const int hc = h * DHEAD;
    const int brow = b * SEQ;
    const int qrow0 = brow + qt * 64 + w * 16;

    uint32_t qAh[4][4], qAl[4][4];
#pragma unroll
    for (int kc = 0; kc < 4; kc++) {
        const __half* bh = qh + (size_t)qrow0 * DMODEL + hc + kc * 16;
        const __half* bl = ql + (size_t)qrow0 * DMODEL + hc + kc * 16;
        qAh[kc][0] = *(const uint32_t*)(bh + (size_t)gid * DMODEL + qc);
        qAh[kc][1] = *(const uint32_t*)(bh + (size_t)(gid + 8) * DMODEL + qc);
        qAh[kc][2] = *(const uint32_t*)(bh + (size_t)gid * DMODEL + qc + 8);
        qAh[kc][3] = *(const uint32_t*)(bh + (size_t)(gid + 8) * DMODEL + qc + 8);
        qAl[kc][0] = *(const uint32_t*)(bl + (size_t)gid * DMODEL + qc);
        qAl[kc][1] = *(const uint32_t*)(bl + (size_t)(gid + 8) * DMODEL + qc);
        qAl[kc][2] = *(const uint32_t*)(bl + (size_t)gid * DMODEL + qc + 8);
        qAl[kc][3] = *(const uint32_t*)(bl + (size_t)(gid + 8) * DMODEL + qc + 8);
    }

    float O[8][4];
#pragma unroll
    for (int t = 0; t < 8; t++)
        O[t][0] = O[t][1] = O[t][2] = O[t][3] = 0.f;
    float m0 = -1e30f, m1 = -1e30f, l0 = 0.f, l1 = 0.f;

    auto load_stage = [&](int kv, int s) {
#pragma unroll
        for (int i = 0; i < 4; i++) {
            int c = tid + i * 128;
            int rr = c >> 3, qq = c & 7;
            size_t g = (size_t)(brow + kv * 64 + rr) * DMODEL + hc + qq * 8;
            int so = s * 4608 + rr * 72 + qq * 8;
            cp16(KH + so, kh + g);
            cp16(KL + so, kl + g);
            cp16(VT + so, v + g);
        }
    };

    const int NT = SEQ / 64;
    load_stage(0, 0); cp_commit();

    for (int kt = 0; kt < NT; kt++) {
        cp_wait<0>();
        __syncthreads();
        if (kt + 1 < NT) { load_stage(kt + 1, (kt + 1) & 1); cp_commit(); }

        const int s = kt & 1;
        const __half* KHs = KH + s * 4608;
        const __half* KLs = KL + s * 4608;
        const __half* VTs = VT + s * 4608;

        float S[8][4];
#pragma unroll
        for (int t = 0; t < 8; t++) {
            S[t][0] = S[t][1] = S[t][2] = S[t][3] = 0.f;
#pragma unroll
            for (int kc = 0; kc < 4; kc++) {
                int koff = (t * 8 + gid) * 72 + kc * 16 + qc;
                uint32_t bh0 = *(const uint32_t*)(KHs + koff);
                uint32_t bh1 = *(const uint32_t*)(KHs + koff + 8);
                uint32_t bl0 = *(const uint32_t*)(KLs + koff);
                uint32_t bl1 = *(const uint32_t*)(KLs + koff + 8);
                mma16816(S[t], qAh[kc], bh0, bh1);
                mma16816(S[t], qAh[kc], bl0, bl1);
                mma16816(S[t], qAl[kc], bh0, bh1);
            }
        }

        float mt0 = -1e30f, mt1 = -1e30f;
#pragma unroll
        for (int t = 0; t < 8; t++) {
            mt0 = fmaxf(mt0, fmaxf(S[t][0], S[t][1]));
            mt1 = fmaxf(mt1, fmaxf(S[t][2], S[t][3]));
        }
        mt0 = fmaxf(mt0, __shfl_xor_sync(0xffffffffu, mt0, 1));
        mt0 = fmaxf(mt0, __shfl_xor_sync(0xffffffffu, mt0, 2));
        mt1 = fmaxf(mt1, __shfl_xor_sync(0xffffffffu, mt1, 1));
        mt1 = fmaxf(mt1, __shfl_xor_sync(0xffffffffu, mt1, 2));
        float mn0 = fmaxf(m0, mt0), mn1 = fmaxf(m1, mt1);
        float al0 = __expf(m0 - mn0), al1 = __expf(m1 - mn1);

        uint32_t pA[4][4];
        float ls0 = 0.f, ls1 = 0.f;
#pragma unroll
        for (int t = 0; t < 8; t++) {
            float p0 = __expf(S[t][0] - mn0);
            float p1 = __expf(S[t][1] - mn0);
            float p2 = __expf(S[t][2] - mn1);
            float p3 = __expf(S[t][3] - mn1);
            ls0 += p0 + p1;
            ls1 += p2 + p3;
            pA[t >> 1][(t & 1) * 2 + 0] = f2u2(p0, p1);
            pA[t >> 1][(t & 1) * 2 + 1] = f2u2(p2, p3);
        }
        ls0 += __shfl_xor_sync(0xffffffffu, ls0, 1);
        ls0 += __shfl_xor_sync(0xffffffffu, ls0, 2);
        ls1 += __shfl_xor_sync(0xffffffffu, ls1, 1);
        ls1 += __shfl_xor_sync(0xffffffffu, ls1, 2);
        l0 = l0 * al0 + ls0;
        l1 = l1 * al1 + ls1;
        m0 = mn0; m1 = mn1;
#pragma unroll
        for (int t = 0; t < 8; t++) {
            O[t][0] *= al0; O[t][1] *= al0;
            O[t][2] *= al1; O[t][3] *= al1;
        }

#pragma unroll
        for (int t = 0; t < 8; t++) {
#pragma unroll
            for (int kc = 0; kc < 4; kc++) {
                int vr = (kc * 16 + qc) * 72 + t * 8 + gid;
                __half x0 = VTs[vr];
                __half x1 = VTs[vr + 72];
                __half x2 = VTs[vr + 8 * 72];
                __half x3 = VTs[vr + 9 * 72];
                mma16816(O[t], pA[kc], h2u(x0, x1), h2u(x2, x3));
            }
        }
    }

    float inv0 = 1.f / l0, inv1 = 1.f / l1;
#pragma unroll
    for (int t = 0; t < 8; t++) {
        *(__half2*)(ctx + (size_t)(qrow0 + gid) * DMODEL + hc + t * 8 + qc) =
            __floats2half2_rn(O[t][0] * inv0, O[t][1] * inv0);
        *(__half2*)(ctx + (size_t)(qrow0 + gid + 8) * DMODEL + hc + t * 8 + qc) =
            __floats2half2_rn(O[t][2] * inv1, O[t][3] * inv1);
    }
}

// ---------------------------------------------------------------------------
// LayerNorm (unchanged)
// ---------------------------------------------------------------------------
__global__ void __launch_bounds__(256) ln_kernel(
    const float* __restrict__ in, const float* __restrict__ g,
    const float* __restrict__ be, float* __restrict__ outf,
    __half* __restrict__ outh)
{
    int row = blockIdx.x;
    int tid = threadIdx.x;
    float4 v = ((const float4*)(in + (size_t)row * DMODEL))[tid];
    float s  = v.x + v.y + v.z + v.w;
    float ss = v.x * v.x + v.y * v.y + v.z * v.z + v.w * v.w;
#pragma unroll
    for (int o = 16; o > 0; o >>= 1) {
        s  += __shfl_down_sync(0xffffffffu, s, o);
        ss += __shfl_down_sync(0xffffffffu, ss, o);
    }
    __shared__ float shs[8], shss[8], smu, srs;
    int lane = tid & 31, wid = tid >> 5;
    if (lane == 0) { shs[wid] = s; shss[wid] = ss; }
    __syncthreads();
    if (tid == 0) {
        float S = 0.f, SS = 0.f;
#pragma unroll
        for (int i = 0; i < 8; i++) { S += shs[i]; SS += shss[i]; }
        float mu = S * (1.f / 1024.f);
        float var = SS * (1.f / 1024.f) - mu * mu;
        smu = mu;
        srs = rsqrtf(var + 1e-5f);
    }
    __syncthreads();
    float mu = smu, rs = srs;
    float4 gv = ((const float4*)g)[tid];
    float4 bv = ((const float4*)be)[tid];
    float4 o;
    o.x = (v.x - mu) * rs * gv.x + bv.x;
    o.y = (v.y - mu) * rs * gv.y + bv.y;
    o.z = (v.z - mu) * rs * gv.z + bv.z;
    o.w = (v.w - mu) * rs * gv.w + bv.w;
    ((float4*)(outf + (size_t)row * DMODEL))[tid] = o;
    if (outh) {
        ((__half2*)(outh + (size_t)row * DMODEL))[2 * tid]     = __floats2half2_rn(o.x, o.y);
        ((__half2*)(outh + (size_t)row * DMODEL))[2 * tid + 1] = __floats2half2_rn(o.z, o.w);
    }
}

extern "C" void kernel_launch(void* const* d_in, const int* in_sizes, int n_in,
                              void* d_out, int out_size) {
    const float* x   = (const float*)d_in[0];
    const float* wq  = (const float*)d_in[1];
    const float* bq  = (const float*)d_in[2];
    const float* wk  = (const float*)d_in[3];
    const float* bk  = (const float*)d_in[4];
    const float* wv  = (const float*)d_in[5];
    const float* bv  = (const float*)d_in[6];
    const float* wo  = (const float*)d_in[7];
    const float* bo  = (const float*)d_in[8];
    const float* w1  = (const float*)d_in[9];
    const float* b1  = (const float*)d_in[10];
    const float* w2  = (const float*)d_in[11];
    const float* b2  = (const float*)d_in[12];
    const float* g1  = (const float*)d_in[13];
    const float* be1 = (const float*)d_in[14];
    const float* g2  = (const float*)d_in[15];
    const float* be2 = (const float*)d_in[16];
    float* out = (float*)d_out;

    void *p;
    cudaGetSymbolAddress(&p, g_xh);    __half* xh   = (__half*)p;
    cudaGetSymbolAddress(&p, g_xl);    __half* xl   = (__half*)p;
    cudaGetSymbolAddress(&p, g_wqTh);  __half* wqTh = (__half*)p;
    cudaGetSymbolAddress(&p, g_wqTl);  __half* wqTl = (__half*)p;
    cudaGetSymbolAddress(&p, g_wkTh);  __half* wkTh = (__half*)p;
    cudaGetSymbolAddress(&p, g_wkTl);  __half* wkTl = (__half*)p;
    cudaGetSymbolAddress(&p, g_wvT);   __half* wvT  = (__half*)p;
    cudaGetSymbolAddress(&p, g_woT);   __half* woT  = (__half*)p;
    cudaGetSymbolAddress(&p, g_w1T);   __half* w1T  = (__half*)p;
    cudaGetSymbolAddress(&p, g_w2T);   __half* w2T  = (__half*)p;
    cudaGetSymbolAddress(&p, g_qrh);   __half* qrh  = (__half*)p;
    cudaGetSymbolAddress(&p, g_qrl);   __half* qrl  = (__half*)p;
    cudaGetSymbolAddress(&p, g_krh);   __half* krh  = (__half*)p;
    cudaGetSymbolAddress(&p, g_krl);   __half* krl  = (__half*)p;
    cudaGetSymbolAddress(&p, g_vh);    __half* vh   = (__half*)p;
    cudaGetSymbolAddress(&p, g_ctx);   __half* ctx  = (__half*)p;
    cudaGetSymbolAddress(&p, g_res1);  float*  res1 = (float*)p;
    cudaGetSymbolAddress(&p, g_hbuf);  float*  hbuf = (float*)p;
    cudaGetSymbolAddress(&p, g_hh);    __half* hh   = (__half*)p;
    cudaGetSymbolAddress(&p, g_ff1);   __half* ff1  = (__half*)p;
    cudaGetSymbolAddress(&p, g_res2);  float*  res2 = (float*)p;

    cudaFuncSetAttribute(gemm_r<false, false, false, true>,
                         cudaFuncAttributeMaxDynamicSharedMemorySize, GR_SMEM);
    cudaFuncSetAttribute(gemm_r<false, true, true, false>,
                         cudaFuncAttributeMaxDynamicSharedMemorySize, GR_SMEM);
    cudaFuncSetAttribute(gemm_r<true, false, false, true>,
                         cudaFuncAttributeMaxDynamicSharedMemorySize, GR_SMEM);
    cudaFuncSetAttribute(gemm_sr,
                         cudaFuncAttributeMaxDynamicSharedMemorySize, GSR_SMEM);
    cudaFuncSetAttribute(attn_kernel,
                         cudaFuncAttributeMaxDynamicSharedMemorySize, ATT_SMEM);

    // 0: x hi/lo split
    convx_kernel<<<(X4 + 255) / 256, 256>>>(x, xh, xl);
    // 1-4: attention-block weight transposes
    dim3 tg1(DMODEL / 32, DMODEL / 32);
    tconv_split<<<tg1, 256>>>(wq, wqTh, wqTl, DMODEL, DMODEL);
    tconv_split<<<tg1, 256>>>(wk, wkTh, wkTl, DMODEL, DMODEL);
    tconv_plain<<<tg1, 256>>>(wv, wvT, DMODEL, DMODEL);
    tconv_plain<<<tg1, 256>>>(wo, woT, DMODEL, DMODEL);

    dim3 grid1(DMODEL / 128, ROWS / 128);   // (8, 64)
    dim3 gridF(DFF / 128,    ROWS / 128);   // (32, 64)

    // 5: Q projection (split + rope)  <- ncu capture slot
    gemm_sr<<<grid1, 256, GSR_SMEM>>>(xh, xl, wqTh, wqTl, bq, qrh, qrl, 0.125f, ROWS, DMODEL, DMODEL);
    // 6: K projection (split + rope)
    gemm_sr<<<grid1, 256, GSR_SMEM>>>(xh, xl, wkTh, wkTl, bk, krh, krl, 1.0f, ROWS, DMODEL, DMODEL);
    // 7: V projection (plain, fp16 out)
    gemm_r<false, false, false, true><<<grid1, 256, GR_SMEM>>>(
        xh, wvT, bv, nullptr, nullptr, vh, ROWS, DMODEL, DMODEL);
    // 8: attention
    attn_kernel<<<dim3(SEQ / 64, NHEADS, BATCH), 128, ATT_SMEM>>>(qrh, qrl, krh, krl, vh, ctx);
    // 9: output projection + residual(x)
    gemm_r<false, true, true, false><<<grid1, 256, GR_SMEM>>>(
        ctx, woT, bo, x, res1, nullptr, ROWS, DMODEL, DMODEL);
    // 10: LN1
    ln_kernel<<<ROWS, 256>>>(res1, g1, be1, hbuf, hh);
    // 11-12: FFN weight transposes
    tconv_plain<<<dim3(DFF / 32, DMODEL / 32), 256>>>(w1, w1T, DMODEL, DFF);
    tconv_plain<<<dim3(DMODEL / 32, DFF / 32), 256>>>(w2, w2T, DFF, DMODEL);
    // 13: FFN1 (relu, fp16 out)
    gemm_r<true, false, false, true><<<gridF, 256, GR_SMEM>>>(
        hh, w1T, b1, nullptr, nullptr, ff1, ROWS, DFF, DMODEL);
    // 14: FFN2 (+resid hbuf, fp32 out)
    gemm_r<false, true, true, false><<<grid1, 256, GR_SMEM>>>(
        ff1, w2T, b2, hbuf, res2, nullptr, ROWS, DMODEL, DFF);
    // 15: LN2 -> output
    ln_kernel<<<ROWS, 256>>>(res2, g2, be2, out, nullptr);
}